// round 5
// baseline (speedup 1.0000x reference)
#include <cuda_runtime.h>
#include <math.h>

#define TS_   256
#define CTS_  512
#define B_    64
#define H_    512
#define K_    10
#define H3_   1536
#define TB_   16384
#define LOG2E 1.44269504088896340736f

static const int OFF_ATTK = TB_ * H_;
static const int OFF_ATTW = TB_ * H_ + TB_ * K_;

typedef unsigned long long u64;

// ---------------- static device scratch ----------------
__device__ float    g_a   [TB_ * K_];
__device__ float    g_b2  [TB_ * K_];
__device__ float    g_kinc[TB_ * K_];
__device__ float    g_phi [TB_ * CTS_];
__device__ float    g_gi  [TB_ * H3_];
__device__ float    g_h   [2 * B_ * H_];
__device__ unsigned g_bar4[128];

__device__ __forceinline__ float ex2f(float x) {
    float r; asm("ex2.approx.ftz.f32 %0, %1;" : "=f"(r) : "f"(x)); return r;
}
__device__ __forceinline__ float sigmf(float x) { return 1.0f / (1.0f + __expf(-x)); }

__device__ __forceinline__ u64 pack2(float lo, float hi) {
    u64 r; asm("mov.b64 %0, {%1, %2};" : "=l"(r) : "f"(lo), "f"(hi)); return r;
}
__device__ __forceinline__ void unpack2(u64 v, float& lo, float& hi) {
    asm("mov.b64 {%0, %1}, %2;" : "=f"(lo), "=f"(hi) : "l"(v));
}
__device__ __forceinline__ u64 ffma2(u64 a, u64 b, u64 c) {
    u64 d; asm("fma.rn.f32x2 %0, %1, %2, %3;" : "=l"(d) : "l"(a), "l"(b), "l"(c)); return d;
}

// ---------------- K0: init ----------------
__global__ void k_init(const float* __restrict__ gru_init) {
    int i = blockIdx.x * 1024 + threadIdx.x;
    g_h[i] = gru_init[i];
    if (i < 128) g_bar4[i] = 0;
}

// ---------------- K1: a_t, b_t, kinc_t ----------------
__global__ __launch_bounds__(256) void k_abk(
    const float* __restrict__ inp,
    const float* __restrict__ Wa, const float* __restrict__ ba,
    const float* __restrict__ Wb, const float* __restrict__ bb,
    const float* __restrict__ Wk, const float* __restrict__ bk)
{
    __shared__ float xs[8 * 516];
    int tid = threadIdx.x;
    int r0 = blockIdx.x * 8;
    #pragma unroll
    for (int c = 0; c < 4; c++) {
        int fi = c * 256 + tid;
        int r = fi >> 7, hq = fi & 127;
        float4 v = *(const float4*)&inp[(r0 + r) * 512 + hq * 4];
        *(float4*)&xs[r * 516 + hq * 4] = v;
    }
    __syncthreads();

    int r = tid >> 5, o = tid & 31;
    if (o >= 30) return;
    const float* wrow; float bias;
    if (o < 10)      { wrow = Wa + o * 512;        bias = ba[o]; }
    else if (o < 20) { wrow = Wb + (o - 10) * 512; bias = bb[o - 10]; }
    else             { wrow = Wk + (o - 20) * 512; bias = bk[o - 20]; }

    const float4* xp = (const float4*)&xs[r * 516];
    const float4* wp = (const float4*)wrow;
    float a0 = 0.f, a1 = 0.f, a2 = 0.f, a3 = 0.f;
    #pragma unroll 8
    for (int q = 0; q < 128; q++) {
        float4 x = xp[q];
        float4 w = __ldg(&wp[q]);
        a0 += x.x * w.x; a1 += x.y * w.y; a2 += x.z * w.z; a3 += x.w * w.w;
    }
    float v = expf((a0 + a1) + (a2 + a3) + bias);
    int row = r0 + r;
    if (o < 10)      g_a   [row * 10 + o]        = v;
    else if (o < 20) g_b2  [row * 10 + (o - 10)] = v * LOG2E;
    else             g_kinc[row * 10 + (o - 20)] = v;
}

// ---------------- K2: cumulative k_t ----------------
__global__ void k_cumsum(const float* __restrict__ att_init, float* __restrict__ out) {
    int j = blockIdx.x * 128 + threadIdx.x;
    if (j >= 640) return;
    float acc = att_init[j];
    #pragma unroll 8
    for (int t = 0; t < TS_; t++) {
        acc += g_kinc[t * 640 + j];
        g_kinc[t * 640 + j] = acc;
        out[OFF_ATTK + t * 640 + j] = acc;
    }
}

// ---------------- K3: phi ----------------
__global__ __launch_bounds__(512) void k_phi() {
    __shared__ float sa[10], sb[10], sk[10];
    int row = blockIdx.x;
    int tid = threadIdx.x;
    if (tid < 10)       sa[tid]      = g_a   [row * 10 + tid];
    else if (tid < 20)  sb[tid - 10] = g_b2  [row * 10 + tid - 10];
    else if (tid < 30)  sk[tid - 20] = g_kinc[row * 10 + tid - 20];
    __syncthreads();
    float s = (float)tid;
    float acc = 0.f;
    #pragma unroll
    for (int k = 0; k < 10; k++) {
        float d = sk[k] - s;
        float e = sb[k] * d * d;
        if (e < 30.f) acc += sa[k] * ex2f(-e);
    }
    g_phi[row * 512 + tid] = acc;
}

// ---------------- GEMM: 128x128 tile, m-paired accumulators, 4 LDS.128/kk ----------------
#define AST 132
#define BST 132

// K4: w = phi @ c_inp (per batch)
__global__ __launch_bounds__(256, 2) void k_gemm_w(
    const float* __restrict__ c_inp, float* __restrict__ outw)
{
    __shared__ float As[16 * AST];
    __shared__ float Bs[16 * BST];
    int tid = threadIdx.x;
    int b  = blockIdx.z;
    int m0 = blockIdx.y * 128, n0 = blockIdx.x * 128;

    int lrow = tid >> 2, lq = tid & 3;
    const float* Ap0 = g_phi + b * 512 + (m0 + lrow) * 32768 + lq * 4;
    const float* Ap1 = Ap0 + 64 * 32768;
    int lk = tid >> 5, nq = tid & 31;
    const float* Bp0 = c_inp + b * 512 + lk * 32768 + n0 + nq * 4;
    const float* Bp1 = Bp0 + 8 * 32768;

    float4 aR0 = *(const float4*)(Ap0);
    float4 aR1 = *(const float4*)(Ap1);
    float4 bR0 = *(const float4*)(Bp0);
    float4 bR1 = *(const float4*)(Bp1);

    int tx = tid & 15, ty = tid >> 4;
    u64 acc[4][8];
    #pragma unroll
    for (int i = 0; i < 4; i++)
        #pragma unroll
        for (int j = 0; j < 8; j++) acc[i][j] = 0ull;

    for (int kt = 0; kt < 32; kt++) {
        __syncthreads();
        As[(lq * 4 + 0) * AST + lrow]      = aR0.x;
        As[(lq * 4 + 1) * AST + lrow]      = aR0.y;
        As[(lq * 4 + 2) * AST + lrow]      = aR0.z;
        As[(lq * 4 + 3) * AST + lrow]      = aR0.w;
        As[(lq * 4 + 0) * AST + lrow + 64] = aR1.x;
        As[(lq * 4 + 1) * AST + lrow + 64] = aR1.y;
        As[(lq * 4 + 2) * AST + lrow + 64] = aR1.z;
        As[(lq * 4 + 3) * AST + lrow + 64] = aR1.w;
        *(float4*)&Bs[lk * BST + nq * 4]       = bR0;
        *(float4*)&Bs[(lk + 8) * BST + nq * 4] = bR1;
        __syncthreads();
        if (kt < 31) {
            aR0 = *(const float4*)(Ap0 + (kt + 1) * 16);
            aR1 = *(const float4*)(Ap1 + (kt + 1) * 16);
            bR0 = *(const float4*)(Bp0 + (kt + 1) * 16 * 32768);
            bR1 = *(const float4*)(Bp1 + (kt + 1) * 16 * 32768);
        }
        #pragma unroll
        for (int kk = 0; kk < 16; kk++) {
            ulonglong2 am01 = *(const ulonglong2*)&As[kk * AST + ty * 8];
            ulonglong2 am23 = *(const ulonglong2*)&As[kk * AST + ty * 8 + 4];
            float4 b0 = *(const float4*)&Bs[kk * BST + tx * 4];
            float4 b1 = *(const float4*)&Bs[kk * BST + tx * 4 + 64];
            u64 av[4] = {am01.x, am01.y, am23.x, am23.y};
            u64 bv[8] = {pack2(b0.x, b0.x), pack2(b0.y, b0.y),
                         pack2(b0.z, b0.z), pack2(b0.w, b0.w),
                         pack2(b1.x, b1.x), pack2(b1.y, b1.y),
                         pack2(b1.z, b1.z), pack2(b1.w, b1.w)};
            #pragma unroll
            for (int i = 0; i < 4; i++)
                #pragma unroll
                for (int j = 0; j < 8; j++)
                    acc[i][j] = ffma2(av[i], bv[j], acc[i][j]);
        }
    }
    float* C = outw + b * 512;
    #pragma unroll
    for (int i = 0; i < 4; i++) {
        int m = m0 + ty * 8 + 2 * i;
        float l0, h0, l1, h1, l2, h2, l3, h3;
        unpack2(acc[i][0], l0, h0); unpack2(acc[i][1], l1, h1);
        unpack2(acc[i][2], l2, h2); unpack2(acc[i][3], l3, h3);
        *(float4*)&C[(size_t)m * 32768 + n0 + tx * 4]       = make_float4(l0, l1, l2, l3);
        *(float4*)&C[(size_t)(m + 1) * 32768 + n0 + tx * 4] = make_float4(h0, h1, h2, h3);
        unpack2(acc[i][4], l0, h0); unpack2(acc[i][5], l1, h1);
        unpack2(acc[i][6], l2, h2); unpack2(acc[i][7], l3, h3);
        *(float4*)&C[(size_t)m * 32768 + n0 + tx * 4 + 64]       = make_float4(l0, l1, l2, l3);
        *(float4*)&C[(size_t)(m + 1) * 32768 + n0 + tx * 4 + 64] = make_float4(h0, h1, h2, h3);
    }
}

// K5: gi = w @ W_ih^T + b_ih
__global__ __launch_bounds__(256, 2) void k_gemm_gi(
    const float* __restrict__ w, const float* __restrict__ W_ih,
    const float* __restrict__ b_ih)
{
    __shared__ float As[16 * AST];
    __shared__ float Bs[16 * BST];
    int tid = threadIdx.x;
    int m0 = blockIdx.y * 128, n0 = blockIdx.x * 128;

    int lrow = tid >> 2, lq = tid & 3;
    const float* Ap0 = w + (m0 + lrow) * 512 + lq * 4;
    const float* Ap1 = Ap0 + 64 * 512;
    const float* Bp0 = W_ih + (n0 + lrow) * 512 + lq * 4;
    const float* Bp1 = Bp0 + 64 * 512;

    float4 aR0 = *(const float4*)(Ap0);
    float4 aR1 = *(const float4*)(Ap1);
    float4 bR0 = *(const float4*)(Bp0);
    float4 bR1 = *(const float4*)(Bp1);

    int tx = tid & 15, ty = tid >> 4;
    u64 acc[4][8];
    #pragma unroll
    for (int i = 0; i < 4; i++)
        #pragma unroll
        for (int j = 0; j < 8; j++) acc[i][j] = 0ull;

    for (int kt = 0; kt < 32; kt++) {
        __syncthreads();
        As[(lq * 4 + 0) * AST + lrow]      = aR0.x;
        As[(lq * 4 + 1) * AST + lrow]      = aR0.y;
        As[(lq * 4 + 2) * AST + lrow]      = aR0.z;
        As[(lq * 4 + 3) * AST + lrow]      = aR0.w;
        As[(lq * 4 + 0) * AST + lrow + 64] = aR1.x;
        As[(lq * 4 + 1) * AST + lrow + 64] = aR1.y;
        As[(lq * 4 + 2) * AST + lrow + 64] = aR1.z;
        As[(lq * 4 + 3) * AST + lrow + 64] = aR1.w;
        Bs[(lq * 4 + 0) * BST + lrow]      = bR0.x;
        Bs[(lq * 4 + 1) * BST + lrow]      = bR0.y;
        Bs[(lq * 4 + 2) * BST + lrow]      = bR0.z;
        Bs[(lq * 4 + 3) * BST + lrow]      = bR0.w;
        Bs[(lq * 4 + 0) * BST + lrow + 64] = bR1.x;
        Bs[(lq * 4 + 1) * BST + lrow + 64] = bR1.y;
        Bs[(lq * 4 + 2) * BST + lrow + 64] = bR1.z;
        Bs[(lq * 4 + 3) * BST + lrow + 64] = bR1.w;
        __syncthreads();
        if (kt < 31) {
            aR0 = *(const float4*)(Ap0 + (kt + 1) * 16);
            aR1 = *(const float4*)(Ap1 + (kt + 1) * 16);
            bR0 = *(const float4*)(Bp0 + (kt + 1) * 16);
            bR1 = *(const float4*)(Bp1 + (kt + 1) * 16);
        }
        #pragma unroll
        for (int kk = 0; kk < 16; kk++) {
            ulonglong2 am01 = *(const ulonglong2*)&As[kk * AST + ty * 8];
            ulonglong2 am23 = *(const ulonglong2*)&As[kk * AST + ty * 8 + 4];
            float4 b0 = *(const float4*)&Bs[kk * BST + tx * 4];
            float4 b1 = *(const float4*)&Bs[kk * BST + tx * 4 + 64];
            u64 av[4] = {am01.x, am01.y, am23.x, am23.y};
            u64 bv[8] = {pack2(b0.x, b0.x), pack2(b0.y, b0.y),
                         pack2(b0.z, b0.z), pack2(b0.w, b0.w),
                         pack2(b1.x, b1.x), pack2(b1.y, b1.y),
                         pack2(b1.z, b1.z), pack2(b1.w, b1.w)};
            #pragma unroll
            for (int i = 0; i < 4; i++)
                #pragma unroll
                for (int j = 0; j < 8; j++)
                    acc[i][j] = ffma2(av[i], bv[j], acc[i][j]);
        }
    }
    float4 bias0 = *(const float4*)&b_ih[n0 + tx * 4];
    float4 bias1 = *(const float4*)&b_ih[n0 + tx * 4 + 64];
    #pragma unroll
    for (int i = 0; i < 4; i++) {
        int m = m0 + ty * 8 + 2 * i;
        float l0, h0, l1, h1, l2, h2, l3, h3;
        unpack2(acc[i][0], l0, h0); unpack2(acc[i][1], l1, h1);
        unpack2(acc[i][2], l2, h2); unpack2(acc[i][3], l3, h3);
        *(float4*)&g_gi[(size_t)m * 1536 + n0 + tx * 4] =
            make_float4(l0 + bias0.x, l1 + bias0.y, l2 + bias0.z, l3 + bias0.w);
        *(float4*)&g_gi[(size_t)(m + 1) * 1536 + n0 + tx * 4] =
            make_float4(h0 + bias0.x, h1 + bias0.y, h2 + bias0.z, h3 + bias0.w);
        unpack2(acc[i][4], l0, h0); unpack2(acc[i][5], l1, h1);
        unpack2(acc[i][6], l2, h2); unpack2(acc[i][7], l3, h3);
        *(float4*)&g_gi[(size_t)m * 1536 + n0 + tx * 4 + 64] =
            make_float4(l0 + bias1.x, l1 + bias1.y, l2 + bias1.z, l3 + bias1.w);
        *(float4*)&g_gi[(size_t)(m + 1) * 1536 + n0 + tx * 4 + 64] =
            make_float4(h0 + bias1.x, h1 + bias1.y, h2 + bias1.z, h3 + bias1.w);
    }
}

// ---------------- K6: persistent sequential GRU ----------------
// 128 blocks (32 ug x 4 bg) x 256 threads; thread = (u = tid&15, bp = tid>>4), 1 batch, 1 unit
#define HS_ST 516
#define SMEM_GRU_BYTES ((16 + 48) * HS_ST * 4)

__global__ __launch_bounds__(256, 1) void k_gru(
    const float* __restrict__ W_hh, const float* __restrict__ b_hh,
    float* __restrict__ out)
{
    extern __shared__ float smemf[];
    float* hs  = smemf;               // [16][HS_ST] batches
    float* Wsm = smemf + 16 * HS_ST;  // [48][HS_ST] rows: gate*16 + u
    int tid = threadIdx.x;
    int ug = blockIdx.x, bg = blockIdx.y;

    // stage W_hh slice (48 rows x 512) once
    for (int f = tid; f < 48 * 128; f += 256) {
        int rr = f >> 7, c = f & 127;
        int gate = rr >> 4, uu = rr & 15;
        float4 v = *(const float4*)&W_hh[(gate * 512 + ug * 16 + uu) * 512 + c * 4];
        *(float4*)&Wsm[rr * HS_ST + c * 4] = v;
    }

    int u  = tid & 15;
    int bp = tid >> 4;
    int gu = ug * 16 + u;
    int gb = bg * 16 + bp;
    float bhr = b_hh[gu], bhz = b_hh[512 + gu], bhn = b_hh[1024 + gu];
    const float* wr = &Wsm[(0  + u) * HS_ST];
    const float* wz = &Wsm[(16 + u) * HS_ST];
    const float* wn = &Wsm[(32 + u) * HS_ST];
    const float* hrow = &hs[bp * HS_ST];
    unsigned bar_target = 0;
    volatile unsigned* bar = &g_bar4[bg * 32];
    __syncthreads();

    for (int t = 0; t < TS_; t++) {
        // gi prefetch (3 scalars, coalesced across u)
        const float* gp = g_gi + (t * 64 + gb) * 1536 + gu;
        float giR = __ldcs(gp);
        float giZ = __ldcs(gp + 512);
        float giN = __ldcs(gp + 1024);

        // stage h_{t-1}: 16 rows x 512 floats = 2048 float4 / 256 threads
        const float4* src = (const float4*)(g_h + (t & 1) * 32768 + bg * 8192);
        #pragma unroll
        for (int c = 0; c < 8; c++) {
            int i = c * 256 + tid;
            float4 v = __ldcg(&src[i]);
            *(float4*)&hs[(i >> 7) * HS_ST + (i & 127) * 4] = v;
        }
        __syncthreads();

        u64 aR = 0, aZ = 0, aN = 0;
        #pragma unroll 8
        for (int hh = 0; hh < 512; hh += 4) {
            ulonglong2 hv = *(const ulonglong2*)&hrow[hh];
            ulonglong2 r2 = *(const ulonglong2*)&wr[hh];
            ulonglong2 z2 = *(const ulonglong2*)&wz[hh];
            ulonglong2 n2 = *(const ulonglong2*)&wn[hh];
            aR = ffma2(hv.x, r2.x, aR);
            aZ = ffma2(hv.x, z2.x, aZ);
            aN = ffma2(hv.x, n2.x, aN);
            aR = ffma2(hv.y, r2.y, aR);
            aZ = ffma2(hv.y, z2.y, aZ);
            aN = ffma2(hv.y, n2.y, aN);
        }
        float lo, hi;
        unpack2(aR, lo, hi); float sR = lo + hi;
        unpack2(aZ, lo, hi); float sZ = lo + hi;
        unpack2(aN, lo, hi); float sN = lo + hi;

        float hprev = hrow[gu & 511];
        float r = sigmf(giR + sR + bhr);
        float z = sigmf(giZ + sZ + bhz);
        float n = tanhf(giN + r * (sN + bhn));
        float hnew = (1.f - z) * n + z * hprev;

        g_h[((t + 1) & 1) * 32768 + gb * 512 + gu] = hnew;
        out[t * 32768 + gb * 512 + gu] = hnew;

        if (t < TS_ - 1) {
            __threadfence();
            __syncthreads();
            if (tid == 0) {
                bar_target += 32;
                atomicAdd((unsigned*)bar, 1u);
                while (*bar < bar_target) { }
            }
            __syncthreads();
        }
    }
}

// ---------------- host ----------------
extern "C" void kernel_launch(void* const* d_in, const int* in_sizes, int n_in,
                              void* d_out, int out_size)
{
    const float* c_inp    = (const float*)d_in[0];
    const float* inp      = (const float*)d_in[1];
    const float* gru_init = (const float*)d_in[2];
    const float* att_init = (const float*)d_in[3];
    const float* Wa = (const float*)d_in[4];  const float* ba = (const float*)d_in[5];
    const float* Wb = (const float*)d_in[6];  const float* bb = (const float*)d_in[7];
    const float* Wk = (const float*)d_in[8];  const float* bk = (const float*)d_in[9];
    const float* W_ih = (const float*)d_in[10]; const float* b_ih = (const float*)d_in[11];
    const float* W_hh = (const float*)d_in[12]; const float* b_hh = (const float*)d_in[13];
    float* out = (float*)d_out;

    cudaFuncSetAttribute(k_gru, cudaFuncAttributeMaxDynamicSharedMemorySize, SMEM_GRU_BYTES);

    k_init   <<<32, 1024>>>(gru_init);
    k_abk    <<<2048, 256>>>(inp, Wa, ba, Wb, bb, Wk, bk);
    k_cumsum <<<5, 128>>>(att_init, out);
    k_phi    <<<16384, 512>>>();
    k_gemm_w <<<dim3(4, 2, 64), 256>>>(c_inp, out + OFF_ATTW);
    k_gemm_gi<<<dim3(12, 128), 256>>>(out + OFF_ATTW, W_ih, b_ih);
    k_gru    <<<dim3(32, 4), 256, SMEM_GRU_BYTES>>>(W_hh, b_hh, out);
}

// round 6
// speedup vs baseline: 1.0724x; 1.0724x over previous
#include <cuda_runtime.h>
#include <math.h>

#define TS_   256
#define CTS_  512
#define B_    64
#define H_    512
#define K_    10
#define H3_   1536
#define TB_   16384
#define LOG2E 1.44269504088896340736f

static const int OFF_ATTK = TB_ * H_;
static const int OFF_ATTW = TB_ * H_ + TB_ * K_;

typedef unsigned long long u64;

// ---------------- static device scratch ----------------
__device__ float    g_a   [TB_ * K_];
__device__ float    g_b2  [TB_ * K_];
__device__ float    g_kinc[TB_ * K_];
__device__ float    g_phi [TB_ * CTS_];
__device__ float    g_gi  [TB_ * H3_];
__device__ float    g_h   [2 * B_ * H_];
__device__ unsigned g_bar4[128];

__device__ __forceinline__ float ex2f(float x) {
    float r; asm("ex2.approx.ftz.f32 %0, %1;" : "=f"(r) : "f"(x)); return r;
}
__device__ __forceinline__ float sigmf(float x) { return 1.0f / (1.0f + __expf(-x)); }

__device__ __forceinline__ u64 pack2(float lo, float hi) {
    u64 r; asm("mov.b64 %0, {%1, %2};" : "=l"(r) : "f"(lo), "f"(hi)); return r;
}
__device__ __forceinline__ void unpack2(u64 v, float& lo, float& hi) {
    asm("mov.b64 {%0, %1}, %2;" : "=f"(lo), "=f"(hi) : "l"(v));
}
__device__ __forceinline__ u64 ffma2(u64 a, u64 b, u64 c) {
    u64 d; asm("fma.rn.f32x2 %0, %1, %2, %3;" : "=l"(d) : "l"(a), "l"(b), "l"(c)); return d;
}

// ---------------- K0: init ----------------
__global__ void k_init(const float* __restrict__ gru_init) {
    int i = blockIdx.x * 1024 + threadIdx.x;
    g_h[i] = gru_init[i];
    if (i < 128) g_bar4[i] = 0;
}

// ---------------- K1: a_t, b_t, kinc_t ----------------
__global__ __launch_bounds__(256) void k_abk(
    const float* __restrict__ inp,
    const float* __restrict__ Wa, const float* __restrict__ ba,
    const float* __restrict__ Wb, const float* __restrict__ bb,
    const float* __restrict__ Wk, const float* __restrict__ bk)
{
    __shared__ float xs[8 * 516];
    int tid = threadIdx.x;
    int r0 = blockIdx.x * 8;
    #pragma unroll
    for (int c = 0; c < 4; c++) {
        int fi = c * 256 + tid;
        int r = fi >> 7, hq = fi & 127;
        float4 v = *(const float4*)&inp[(r0 + r) * 512 + hq * 4];
        *(float4*)&xs[r * 516 + hq * 4] = v;
    }
    __syncthreads();

    int r = tid >> 5, o = tid & 31;
    if (o >= 30) return;
    const float* wrow; float bias;
    if (o < 10)      { wrow = Wa + o * 512;        bias = ba[o]; }
    else if (o < 20) { wrow = Wb + (o - 10) * 512; bias = bb[o - 10]; }
    else             { wrow = Wk + (o - 20) * 512; bias = bk[o - 20]; }

    const float4* xp = (const float4*)&xs[r * 516];
    const float4* wp = (const float4*)wrow;
    float a0 = 0.f, a1 = 0.f, a2 = 0.f, a3 = 0.f;
    #pragma unroll 8
    for (int q = 0; q < 128; q++) {
        float4 x = xp[q];
        float4 w = __ldg(&wp[q]);
        a0 += x.x * w.x; a1 += x.y * w.y; a2 += x.z * w.z; a3 += x.w * w.w;
    }
    float v = expf((a0 + a1) + (a2 + a3) + bias);
    int row = r0 + r;
    if (o < 10)      g_a   [row * 10 + o]        = v;
    else if (o < 20) g_b2  [row * 10 + (o - 10)] = v * LOG2E;
    else             g_kinc[row * 10 + (o - 20)] = v;
}

// ---------------- K2: cumulative k_t ----------------
__global__ void k_cumsum(const float* __restrict__ att_init, float* __restrict__ out) {
    int j = blockIdx.x * 128 + threadIdx.x;
    if (j >= 640) return;
    float acc = att_init[j];
    #pragma unroll 8
    for (int t = 0; t < TS_; t++) {
        acc += g_kinc[t * 640 + j];
        g_kinc[t * 640 + j] = acc;
        out[OFF_ATTK + t * 640 + j] = acc;
    }
}

// ---------------- K3: phi ----------------
__global__ __launch_bounds__(512) void k_phi() {
    __shared__ float sa[10], sb[10], sk[10];
    int row = blockIdx.x;
    int tid = threadIdx.x;
    if (tid < 10)       sa[tid]      = g_a   [row * 10 + tid];
    else if (tid < 20)  sb[tid - 10] = g_b2  [row * 10 + tid - 10];
    else if (tid < 30)  sk[tid - 20] = g_kinc[row * 10 + tid - 20];
    __syncthreads();
    float s = (float)tid;
    float acc = 0.f;
    #pragma unroll
    for (int k = 0; k < 10; k++) {
        float d = sk[k] - s;
        float e = sb[k] * d * d;
        if (e < 30.f) acc += sa[k] * ex2f(-e);
    }
    g_phi[row * 512 + tid] = acc;
}

// ---------------- GEMM common: 128x128 tile, 8x8/thread, f32x2 (R3 proven) ----------------
#define AST 264
#define BST 132

// K4: w = phi @ c_inp (per batch)
__global__ __launch_bounds__(256, 2) void k_gemm_w(
    const float* __restrict__ c_inp, float* __restrict__ outw)
{
    __shared__ float As2[16 * AST];
    __shared__ float Bs [16 * BST];
    int tid = threadIdx.x;
    int b  = blockIdx.z;
    int m0 = blockIdx.y * 128, n0 = blockIdx.x * 128;

    int lrow = tid >> 2, lq = tid & 3;
    const float* Ap0 = g_phi + b * 512 + (m0 + lrow) * 32768 + lq * 4;
    const float* Ap1 = Ap0 + 64 * 32768;
    int lk = tid >> 5, nq = tid & 31;
    const float* Bp0 = c_inp + b * 512 + lk * 32768 + n0 + nq * 4;
    const float* Bp1 = Bp0 + 8 * 32768;

    float4 aR0 = *(const float4*)(Ap0);
    float4 aR1 = *(const float4*)(Ap1);
    float4 bR0 = *(const float4*)(Bp0);
    float4 bR1 = *(const float4*)(Bp1);

    int tx = tid & 15, ty = tid >> 4;
    u64 acc[8][4];
    #pragma unroll
    for (int i = 0; i < 8; i++)
        #pragma unroll
        for (int j = 0; j < 4; j++) acc[i][j] = 0ull;

    for (int kt = 0; kt < 32; kt++) {
        __syncthreads();
        {
            int m = 2 * lrow;
            *(u64*)&As2[(lq * 4 + 0) * AST + m]       = pack2(aR0.x, aR0.x);
            *(u64*)&As2[(lq * 4 + 1) * AST + m]       = pack2(aR0.y, aR0.y);
            *(u64*)&As2[(lq * 4 + 2) * AST + m]       = pack2(aR0.z, aR0.z);
            *(u64*)&As2[(lq * 4 + 3) * AST + m]       = pack2(aR0.w, aR0.w);
            *(u64*)&As2[(lq * 4 + 0) * AST + m + 128] = pack2(aR1.x, aR1.x);
            *(u64*)&As2[(lq * 4 + 1) * AST + m + 128] = pack2(aR1.y, aR1.y);
            *(u64*)&As2[(lq * 4 + 2) * AST + m + 128] = pack2(aR1.z, aR1.z);
            *(u64*)&As2[(lq * 4 + 3) * AST + m + 128] = pack2(aR1.w, aR1.w);
            *(float4*)&Bs[lk * BST + nq * 4]       = bR0;
            *(float4*)&Bs[(lk + 8) * BST + nq * 4] = bR1;
        }
        __syncthreads();
        if (kt < 31) {
            aR0 = *(const float4*)(Ap0 + (kt + 1) * 16);
            aR1 = *(const float4*)(Ap1 + (kt + 1) * 16);
            bR0 = *(const float4*)(Bp0 + (kt + 1) * 16 * 32768);
            bR1 = *(const float4*)(Bp1 + (kt + 1) * 16 * 32768);
        }
        #pragma unroll
        for (int kk = 0; kk < 16; kk++) {
            ulonglong2 a01 = *(const ulonglong2*)&As2[kk * AST + 8 * ty];
            ulonglong2 a23 = *(const ulonglong2*)&As2[kk * AST + 8 * ty + 4];
            ulonglong2 a45 = *(const ulonglong2*)&As2[kk * AST + 8 * ty + 128];
            ulonglong2 a67 = *(const ulonglong2*)&As2[kk * AST + 8 * ty + 132];
            ulonglong2 b01 = *(const ulonglong2*)&Bs[kk * BST + tx * 4];
            ulonglong2 b23 = *(const ulonglong2*)&Bs[kk * BST + tx * 4 + 64];
            u64 av[8] = {a01.x, a01.y, a23.x, a23.y, a45.x, a45.y, a67.x, a67.y};
            u64 bv[4] = {b01.x, b01.y, b23.x, b23.y};
            #pragma unroll
            for (int i = 0; i < 8; i++)
                #pragma unroll
                for (int j = 0; j < 4; j++)
                    acc[i][j] = ffma2(av[i], bv[j], acc[i][j]);
        }
    }
    float* C = outw + b * 512;
    #pragma unroll
    for (int i = 0; i < 8; i++) {
        int m = m0 + ((i < 4) ? (ty * 4 + i) : (ty * 4 + 64 + i - 4));
        float c0, c1, c2, c3;
        unpack2(acc[i][0], c0, c1); unpack2(acc[i][1], c2, c3);
        *(float4*)&C[(size_t)m * 32768 + n0 + tx * 4] = make_float4(c0, c1, c2, c3);
        unpack2(acc[i][2], c0, c1); unpack2(acc[i][3], c2, c3);
        *(float4*)&C[(size_t)m * 32768 + n0 + tx * 4 + 64] = make_float4(c0, c1, c2, c3);
    }
}

// K5: gi = w @ W_ih^T + b_ih
__global__ __launch_bounds__(256, 2) void k_gemm_gi(
    const float* __restrict__ w, const float* __restrict__ W_ih,
    const float* __restrict__ b_ih)
{
    __shared__ float As2[16 * AST];
    __shared__ float Bs [16 * BST];
    int tid = threadIdx.x;
    int m0 = blockIdx.y * 128, n0 = blockIdx.x * 128;

    int lrow = tid >> 2, lq = tid & 3;
    const float* Ap0 = w + (m0 + lrow) * 512 + lq * 4;
    const float* Ap1 = Ap0 + 64 * 512;
    const float* Bp0 = W_ih + (n0 + lrow) * 512 + lq * 4;
    const float* Bp1 = Bp0 + 64 * 512;

    float4 aR0 = *(const float4*)(Ap0);
    float4 aR1 = *(const float4*)(Ap1);
    float4 bR0 = *(const float4*)(Bp0);
    float4 bR1 = *(const float4*)(Bp1);

    int tx = tid & 15, ty = tid >> 4;
    u64 acc[8][4];
    #pragma unroll
    for (int i = 0; i < 8; i++)
        #pragma unroll
        for (int j = 0; j < 4; j++) acc[i][j] = 0ull;

    for (int kt = 0; kt < 32; kt++) {
        __syncthreads();
        {
            int m = 2 * lrow;
            *(u64*)&As2[(lq * 4 + 0) * AST + m]       = pack2(aR0.x, aR0.x);
            *(u64*)&As2[(lq * 4 + 1) * AST + m]       = pack2(aR0.y, aR0.y);
            *(u64*)&As2[(lq * 4 + 2) * AST + m]       = pack2(aR0.z, aR0.z);
            *(u64*)&As2[(lq * 4 + 3) * AST + m]       = pack2(aR0.w, aR0.w);
            *(u64*)&As2[(lq * 4 + 0) * AST + m + 128] = pack2(aR1.x, aR1.x);
            *(u64*)&As2[(lq * 4 + 1) * AST + m + 128] = pack2(aR1.y, aR1.y);
            *(u64*)&As2[(lq * 4 + 2) * AST + m + 128] = pack2(aR1.z, aR1.z);
            *(u64*)&As2[(lq * 4 + 3) * AST + m + 128] = pack2(aR1.w, aR1.w);
            Bs[(lq * 4 + 0) * BST + lrow]       = bR0.x;
            Bs[(lq * 4 + 1) * BST + lrow]       = bR0.y;
            Bs[(lq * 4 + 2) * BST + lrow]       = bR0.z;
            Bs[(lq * 4 + 3) * BST + lrow]       = bR0.w;
            Bs[(lq * 4 + 0) * BST + lrow + 64]  = bR1.x;
            Bs[(lq * 4 + 1) * BST + lrow + 64]  = bR1.y;
            Bs[(lq * 4 + 2) * BST + lrow + 64]  = bR1.z;
            Bs[(lq * 4 + 3) * BST + lrow + 64]  = bR1.w;
        }
        __syncthreads();
        if (kt < 31) {
            aR0 = *(const float4*)(Ap0 + (kt + 1) * 16);
            aR1 = *(const float4*)(Ap1 + (kt + 1) * 16);
            bR0 = *(const float4*)(Bp0 + (kt + 1) * 16);
            bR1 = *(const float4*)(Bp1 + (kt + 1) * 16);
        }
        #pragma unroll
        for (int kk = 0; kk < 16; kk++) {
            ulonglong2 a01 = *(const ulonglong2*)&As2[kk * AST + 8 * ty];
            ulonglong2 a23 = *(const ulonglong2*)&As2[kk * AST + 8 * ty + 4];
            ulonglong2 a45 = *(const ulonglong2*)&As2[kk * AST + 8 * ty + 128];
            ulonglong2 a67 = *(const ulonglong2*)&As2[kk * AST + 8 * ty + 132];
            ulonglong2 b01 = *(const ulonglong2*)&Bs[kk * BST + tx * 4];
            ulonglong2 b23 = *(const ulonglong2*)&Bs[kk * BST + tx * 4 + 64];
            u64 av[8] = {a01.x, a01.y, a23.x, a23.y, a45.x, a45.y, a67.x, a67.y};
            u64 bv[4] = {b01.x, b01.y, b23.x, b23.y};
            #pragma unroll
            for (int i = 0; i < 8; i++)
                #pragma unroll
                for (int j = 0; j < 4; j++)
                    acc[i][j] = ffma2(av[i], bv[j], acc[i][j]);
        }
    }
    float4 bias0 = *(const float4*)&b_ih[n0 + tx * 4];
    float4 bias1 = *(const float4*)&b_ih[n0 + tx * 4 + 64];
    #pragma unroll
    for (int i = 0; i < 8; i++) {
        int m = m0 + ((i < 4) ? (ty * 4 + i) : (ty * 4 + 64 + i - 4));
        float c0, c1, c2, c3;
        unpack2(acc[i][0], c0, c1); unpack2(acc[i][1], c2, c3);
        *(float4*)&g_gi[(size_t)m * 1536 + n0 + tx * 4] =
            make_float4(c0 + bias0.x, c1 + bias0.y, c2 + bias0.z, c3 + bias0.w);
        unpack2(acc[i][2], c0, c1); unpack2(acc[i][3], c2, c3);
        *(float4*)&g_gi[(size_t)m * 1536 + n0 + tx * 4 + 64] =
            make_float4(c0 + bias1.x, c1 + bias1.y, c2 + bias1.z, c3 + bias1.w);
    }
}

// ---------------- K6: persistent sequential GRU ----------------
// grid (32 ug, 4 bg) x 256 threads; thread = (u = tid>>4, bp = tid&15), 1 cell each.
// Weight LDS stay warp-broadcast (2 u-rows per warp); h LDS are 256B (16 bp-rows).
#define HS_ST 516
#define SMEM_GRU_BYTES ((16 + 48) * HS_ST * 4)

__global__ __launch_bounds__(256, 1) void k_gru(
    const float* __restrict__ W_hh, const float* __restrict__ b_hh,
    float* __restrict__ out)
{
    extern __shared__ float smemf[];
    float* hs  = smemf;               // [16][HS_ST] batches
    float* Wsm = smemf + 16 * HS_ST;  // [48][HS_ST] rows: gate*16 + u
    int tid = threadIdx.x;
    int ug = blockIdx.x, bg = blockIdx.y;

    // stage W_hh slice (48 rows x 512) once
    for (int f = tid; f < 48 * 128; f += 256) {
        int rr = f >> 7, c = f & 127;
        int gate = rr >> 4, uu = rr & 15;
        float4 v = *(const float4*)&W_hh[(gate * 512 + ug * 16 + uu) * 512 + c * 4];
        *(float4*)&Wsm[rr * HS_ST + c * 4] = v;
    }

    int u  = tid >> 4;        // 2 distinct per warp -> broadcast weight loads
    int bp = tid & 15;        // 16 distinct per warp
    int gu = ug * 16 + u;
    int gb = bg * 16 + bp;
    float bhr = b_hh[gu], bhz = b_hh[512 + gu], bhn = b_hh[1024 + gu];
    const float* wr = &Wsm[(0  + u) * HS_ST];
    const float* wz = &Wsm[(16 + u) * HS_ST];
    const float* wn = &Wsm[(32 + u) * HS_ST];
    const float* hrow = &hs[bp * HS_ST];
    unsigned bar_target = 0;
    volatile unsigned* bar = &g_bar4[bg * 32];
    __syncthreads();

    for (int t = 0; t < TS_; t++) {
        // gi prefetch (3 scalars)
        const float* gp = g_gi + (t * 64 + gb) * 1536 + gu;
        float giR = __ldcs(gp);
        float giZ = __ldcs(gp + 512);
        float giN = __ldcs(gp + 1024);

        // stage h_{t-1}: 16 rows x 512 floats = 2048 float4 / 256 threads
        const float4* src = (const float4*)(g_h + (t & 1) * 32768 + bg * 8192);
        #pragma unroll
        for (int c = 0; c < 8; c++) {
            int i = c * 256 + tid;
            float4 v = __ldcg(&src[i]);
            *(float4*)&hs[(i >> 7) * HS_ST + (i & 127) * 4] = v;
        }
        __syncthreads();

        u64 aR = 0, aZ = 0, aN = 0;
        #pragma unroll 8
        for (int hh = 0; hh < 512; hh += 4) {
            ulonglong2 hv = *(const ulonglong2*)&hrow[hh];
            ulonglong2 r2 = *(const ulonglong2*)&wr[hh];
            ulonglong2 z2 = *(const ulonglong2*)&wz[hh];
            ulonglong2 n2 = *(const ulonglong2*)&wn[hh];
            aR = ffma2(hv.x, r2.x, aR);
            aZ = ffma2(hv.x, z2.x, aZ);
            aN = ffma2(hv.x, n2.x, aN);
            aR = ffma2(hv.y, r2.y, aR);
            aZ = ffma2(hv.y, z2.y, aZ);
            aN = ffma2(hv.y, n2.y, aN);
        }
        float lo, hi;
        unpack2(aR, lo, hi); float sR = lo + hi;
        unpack2(aZ, lo, hi); float sZ = lo + hi;
        unpack2(aN, lo, hi); float sN = lo + hi;

        float hprev = hrow[gu & 511];
        float r = sigmf(giR + sR + bhr);
        float z = sigmf(giZ + sZ + bhz);
        float n = tanhf(giN + r * (sN + bhn));
        float hnew = (1.f - z) * n + z * hprev;

        g_h[((t + 1) & 1) * 32768 + gb * 512 + gu] = hnew;
        out[t * 32768 + gb * 512 + gu] = hnew;

        if (t < TS_ - 1) {
            __threadfence();
            __syncthreads();
            if (tid == 0) {
                bar_target += 32;
                atomicAdd((unsigned*)bar, 1u);
                while (*bar < bar_target) { }
            }
            __syncthreads();
        }
    }
}

// ---------------- host ----------------
extern "C" void kernel_launch(void* const* d_in, const int* in_sizes, int n_in,
                              void* d_out, int out_size)
{
    const float* c_inp    = (const float*)d_in[0];
    const float* inp      = (const float*)d_in[1];
    const float* gru_init = (const float*)d_in[2];
    const float* att_init = (const float*)d_in[3];
    const float* Wa = (const float*)d_in[4];  const float* ba = (const float*)d_in[5];
    const float* Wb = (const float*)d_in[6];  const float* bb = (const float*)d_in[7];
    const float* Wk = (const float*)d_in[8];  const float* bk = (const float*)d_in[9];
    const float* W_ih = (const float*)d_in[10]; const float* b_ih = (const float*)d_in[11];
    const float* W_hh = (const float*)d_in[12]; const float* b_hh = (const float*)d_in[13];
    float* out = (float*)d_out;

    cudaFuncSetAttribute(k_gru, cudaFuncAttributeMaxDynamicSharedMemorySize, SMEM_GRU_BYTES);

    k_init   <<<32, 1024>>>(gru_init);
    k_abk    <<<2048, 256>>>(inp, Wa, ba, Wb, bb, Wk, bk);
    k_cumsum <<<5, 128>>>(att_init, out);
    k_phi    <<<16384, 512>>>();
    k_gemm_w <<<dim3(4, 2, 64), 256>>>(c_inp, out + OFF_ATTW);
    k_gemm_gi<<<dim3(12, 128), 256>>>(out + OFF_ATTW, W_ih, b_ih);
    k_gru    <<<dim3(32, 4), 256, SMEM_GRU_BYTES>>>(W_hh, b_hh, out);
}